// round 11
// baseline (speedup 1.0000x reference)
#include <cuda_runtime.h>
#include <cooperative_groups.h>

namespace cg = cooperative_groups;

// Problem constants
#define B_    128
#define T_    1024
#define H_    512
#define I_    64
#define KA    576              // augmented K = H + I
#define NCTA  128
#define NTHR  512              // 16 warps: 4/SMSP for latency hiding
#define NWARP 16
#define HT    16               // h-rows per CTA
#define BT    32               // b-cols per CTA
#define C1    0.9f
#define C2    0.1f

// smem floats: wpk[KA][16] + hs[HT][BT] + red[8 hp][16 w][32 lane] f32x2
#define WPK_F   (KA * 16)              // 9216
#define HS_F    (HT * BT)              // 512
#define RED_F   (8 * NWARP * 32 * 2)   // 8192
#define SMEM_FLOATS (WPK_F + HS_F + RED_F)
#define SMEM_BYTES  (SMEM_FLOATS * 4)

// ---- global scratch (__device__ globals: allocation-free rule) ----
__device__ float g_S[2][H_ * B_];          // double-buffered sigmoid(h)
__device__ float g_xT[T_ * I_ * B_];       // x transposed to [t][i][b]

__device__ __forceinline__ void fma2(unsigned long long &acc,
                                     unsigned long long a,
                                     unsigned long long b) {
    asm("fma.rn.f32x2 %0, %1, %2, %0;" : "+l"(acc) : "l"(a), "l"(b));
}

__device__ __forceinline__ float sigmoidf_(float x) {
    return 1.0f / (1.0f + __expf(-x));
}

__global__ void __launch_bounds__(NTHR, 1)
rnn_coop_kernel(const float* __restrict__ x,      // [B,T,I]
                const float* __restrict__ W_in,   // [H,I]
                const float* __restrict__ W_h,    // [H,H]
                const float* __restrict__ sigma,  // [H,T,B]
                const float* __restrict__ h0,     // [H,B]
                float* __restrict__ out)          // [B,T,H] ++ [H,B]
{
    extern __shared__ float sm[];
    float*  wpk  = sm;                     // [KA][16] interleaved W rows
    float*  hs   = sm + WPK_F;             // [HT][BT] h tile
    float2* redf = (float2*)(sm + WPK_F + HS_F);   // [8 hp][16 w][32 lane]
    float*  ts   = sm + WPK_F + HS_F;      // transpose tile alias (<= RED_F)

    cg::grid_group grid = cg::this_grid();

    const int tid  = threadIdx.x;
    const int warp = tid >> 5;
    const int lane = tid & 31;
    const int cta  = blockIdx.x;
    const int h0r  = (cta >> 2) * HT;      // 32 h-tiles
    const int b0   = (cta & 3)  * BT;      // 4 b-tiles

    // ---- one-time: stage interleaved weights wpk[k][j] = W_aug[h0r+j][k]
    {
        // 16 rows x 144 float4 = 2304 tasks
        #pragma unroll
        for (int i = 0; i < 5; ++i) {
            int idx = i * NTHR + tid;
            if (idx < 2304) {
                int j  = idx / 144;
                int k4 = idx % 144;
                float4 w4 = (k4 < 128)
                    ? *(const float4*)(W_h  + (size_t)(h0r + j) * H_ + 4 * k4)
                    : *(const float4*)(W_in + (size_t)(h0r + j) * I_ + 4 * k4 - 512);
                wpk[(4 * k4 + 0) * 16 + j] = w4.x;
                wpk[(4 * k4 + 1) * 16 + j] = w4.y;
                wpk[(4 * k4 + 2) * 16 + j] = w4.z;
                wpk[(4 * k4 + 3) * 16 + j] = w4.w;
            }
        }
    }

    // ---- one-time: transpose x[B,T,I] -> g_xT[t][i][b] (first 256 threads)
    // tiles: 4 b-blocks x 2 i-blocks x 1024 t = 8192; 64 per CTA
    for (int tile = cta; tile < 8192; tile += NCTA) {
        int tb = tile & 3;
        int ti = (tile >> 2) & 1;
        int tt = tile >> 3;
        if (tid < 256) {   // load + transpose into ts[i][b] (pad 33)
            int row = tid >> 3;            // b-row 0..31
            int c4  = tid & 7;             // i-quad 0..7
            float4 v = *(const float4*)(x + (size_t)(tb * 32 + row) * (T_ * I_)
                                          + (size_t)tt * I_ + ti * 32 + 4 * c4);
            ts[(4 * c4 + 0) * 33 + row] = v.x;
            ts[(4 * c4 + 1) * 33 + row] = v.y;
            ts[(4 * c4 + 2) * 33 + row] = v.z;
            ts[(4 * c4 + 3) * 33 + row] = v.w;
        }
        __syncthreads();
        if (tid < 256) {   // write coalesced
            int irow = tid >> 3;           // i-row 0..31
            int b4   = tid & 7;            // b-quad 0..7
            float4 v;
            v.x = ts[irow * 33 + 4 * b4 + 0];
            v.y = ts[irow * 33 + 4 * b4 + 1];
            v.z = ts[irow * 33 + 4 * b4 + 2];
            v.w = ts[irow * 33 + 4 * b4 + 3];
            __stcg((float4*)(g_xT + ((size_t)tt * I_ + ti * 32 + irow) * B_
                                  + tb * 32 + 4 * b4), v);
        }
        __syncthreads();
    }

    // ---- init h tile + publish sigmoid(h0) into buffer 0
    {
        int hl = tid >> 5, bl = tid & 31;      // 512 tasks exactly
        float h = h0[(size_t)(h0r + hl) * B_ + b0 + bl];
        hs[hl * BT + bl] = h;
        __stcg(&g_S[0][(size_t)(h0r + hl) * B_ + b0 + bl], sigmoidf_(h));
    }
    grid.sync();

    const int uh = tid >> 5;               // update-phase h row (=warp, 0..15)
    const int ub = lane;                   // update-phase b

    int p = 0;
    for (int t = 0; t < T_; ++t) {
        // prefetch sigma for the update phase (1 value/thread, coalesced)
        float sgv = __ldg(sigma + ((size_t)(h0r + uh) * T_ + t) * B_ + b0 + ub);

        // ---- GEMM: CTA covers 16h x 32b, K-split 16 (32 S-k + 4 x-k each)
        unsigned long long acc[8];
        #pragma unroll
        for (int i = 0; i < 8; ++i) acc[i] = 0ull;

        {   // S part: k in [32*warp, 32*warp+32)
            const float* sp = g_S[p] + (size_t)(32 * warp) * B_ + b0 + lane;
            const float* wq = wpk + (32 * warp) * 16;
            float pre[8];
            #pragma unroll
            for (int j = 0; j < 8; ++j) pre[j] = __ldcg(sp + j * B_);
            #pragma unroll
            for (int kk = 0; kk < 32; kk += 8) {
                float cur[8];
                #pragma unroll
                for (int j = 0; j < 8; ++j) cur[j] = pre[j];
                if (kk < 24) {
                    const float* spn = sp + (size_t)(kk + 8) * B_;
                    #pragma unroll
                    for (int j = 0; j < 8; ++j) pre[j] = __ldcg(spn + j * B_);
                }
                #pragma unroll
                for (int j = 0; j < 8; ++j) {
                    unsigned long long sd;
                    asm("mov.b64 %0, {%1, %1};" : "=l"(sd) : "f"(cur[j]));
                    const ulonglong2* w2 = (const ulonglong2*)(wq + (kk + j) * 16);
                    ulonglong2 wa = w2[0], wb = w2[1], wc = w2[2], wd = w2[3];
                    fma2(acc[0], wa.x, sd); fma2(acc[1], wa.y, sd);
                    fma2(acc[2], wb.x, sd); fma2(acc[3], wb.y, sd);
                    fma2(acc[4], wc.x, sd); fma2(acc[5], wc.y, sd);
                    fma2(acc[6], wd.x, sd); fma2(acc[7], wd.y, sd);
                }
            }
        }
        {   // x part: kx in [4*warp, 4*warp+4)
            const float* xp = g_xT + ((size_t)t * I_ + 4 * warp) * B_ + b0 + lane;
            const float* wq = wpk + (512 + 4 * warp) * 16;
            float xv[4];
            #pragma unroll
            for (int j = 0; j < 4; ++j) xv[j] = __ldcg(xp + j * B_);
            #pragma unroll
            for (int j = 0; j < 4; ++j) {
                unsigned long long sd;
                asm("mov.b64 %0, {%1, %1};" : "=l"(sd) : "f"(xv[j]));
                const ulonglong2* w2 = (const ulonglong2*)(wq + j * 16);
                ulonglong2 wa = w2[0], wb = w2[1], wc = w2[2], wd = w2[3];
                fma2(acc[0], wa.x, sd); fma2(acc[1], wa.y, sd);
                fma2(acc[2], wb.x, sd); fma2(acc[3], wb.y, sd);
                fma2(acc[4], wc.x, sd); fma2(acc[5], wc.y, sd);
                fma2(acc[6], wd.x, sd); fma2(acc[7], wd.y, sd);
            }
        }

        // ---- store K-split partials: red[hp][warp][lane], conflict-free
        #pragma unroll
        for (int h = 0; h < 8; ++h) {
            float2 v;
            v.x = __uint_as_float((unsigned)acc[h]);
            v.y = __uint_as_float((unsigned)(acc[h] >> 32));
            redf[(h * NWARP + warp) * 32 + lane] = v;
        }
        __syncthreads();

        // ---- sum 16 partials + leaky update (1 (h,b) per thread, 512 total)
        {
            const float* rb = (const float*)redf;
            int pair = uh >> 1, comp = uh & 1;
            float s = 0.f;
            #pragma unroll
            for (int w = 0; w < NWARP; ++w)
                s += rb[((pair * NWARP + w) * 32 + ub) * 2 + comp];
            float hn = C1 * hs[uh * BT + ub] + C2 * (s + sgv);
            hs[uh * BT + ub] = hn;
            __stcg(&g_S[1 - p][(size_t)(h0r + uh) * B_ + b0 + ub], sigmoidf_(hn));
        }
        __syncthreads();

        // ---- coalesced out tile [B,T,H]
        if (tid < 128) {
            int bb = tid >> 2, hq = (tid & 3) * 4;
            float4 v;
            v.x = hs[(hq + 0) * BT + bb];
            v.y = hs[(hq + 1) * BT + bb];
            v.z = hs[(hq + 2) * BT + bb];
            v.w = hs[(hq + 3) * BT + bb];
            *(float4*)(out + ((size_t)(b0 + bb) * T_ + t) * H_ + h0r + hq) = v;
        }

        grid.sync();
        p ^= 1;
    }

    // ---- h_last [H,B] appended after out [B,T,H]
    if (tid < 128) {
        int hl = tid >> 3, q = (tid & 7) * 4;
        float4 v = *(const float4*)(hs + hl * BT + q);
        *(float4*)(out + (size_t)B_ * T_ * H_ + (size_t)(h0r + hl) * B_ + b0 + q) = v;
    }
}

extern "C" void kernel_launch(void* const* d_in, const int* in_sizes, int n_in,
                              void* d_out, int out_size) {
    const float* x    = (const float*)d_in[0];
    const float* W_in = (const float*)d_in[1];
    const float* W_h  = (const float*)d_in[2];
    const float* sg   = (const float*)d_in[3];
    const float* h0   = (const float*)d_in[4];
    float* out = (float*)d_out;

    static int smem_set = 0;
    if (!smem_set) {
        cudaFuncSetAttribute(rnn_coop_kernel,
                             cudaFuncAttributeMaxDynamicSharedMemorySize, SMEM_BYTES);
        smem_set = 1;
    }

    cudaLaunchConfig_t cfg = {};
    cfg.gridDim  = dim3(NCTA, 1, 1);
    cfg.blockDim = dim3(NTHR, 1, 1);
    cfg.dynamicSmemBytes = SMEM_BYTES;
    cfg.stream = 0;
    cudaLaunchAttribute attr[1];
    attr[0].id = cudaLaunchAttributeCooperative;
    attr[0].val.cooperative = 1;
    cfg.attrs = attr;
    cfg.numAttrs = 1;

    cudaLaunchKernelEx(&cfg, rnn_coop_kernel, x, W_in, W_h, sg, h0, out);
}